// round 14
// baseline (speedup 1.0000x reference)
#include <cuda_runtime.h>
#include <math.h>

#define EPSLN 1e-5f

// ---------------- device scratch ----------------
__device__ float g_qwT[128 * 128];
__device__ float g_kwT[128 * 128];
__device__ float g_outwT[64 * 128];
__device__ float g_wihT[128 * 384];
__device__ float g_c1T[128 * 128];
__device__ float g_c2T[128 * 128];
__device__ float g_q[128 * 128];        // (NT, E)
__device__ float g_kT[8 * 128 * 512];   // (B, E, T)
__device__ float g_gi[128 * 8 * 384];   // (t, b, 3H)

typedef unsigned long long u64;

__device__ __forceinline__ float tanhfast(float x) {
    float y;
    asm("tanh.approx.f32 %0, %1;" : "=f"(y) : "f"(x));
    return y;
}
__device__ __forceinline__ float sigfast(float x) {
    return fmaf(0.5f, tanhfast(0.5f * x), 0.5f);
}
__device__ __forceinline__ u64 fma2(u64 a, u64 b, u64 c) {
    u64 d;
    asm("fma.rn.f32x2 %0, %1, %2, %3;" : "=l"(d) : "l"(a), "l"(b), "l"(c));
    return d;
}
__device__ __forceinline__ u64 add2(u64 a, u64 b) {
    u64 d;
    asm("add.rn.f32x2 %0, %1, %2;" : "=l"(d) : "l"(a), "l"(b));
    return d;
}
__device__ __forceinline__ u64 pack2(float lo, float hi) {
    u64 r;
    asm("mov.b64 %0, {%1,%2};" : "=l"(r) : "f"(lo), "f"(hi));
    return r;
}
__device__ __forceinline__ float2 unpack2(u64 v) {
    float2 f;
    asm("mov.b64 {%0,%1}, %2;" : "=f"(f.x), "=f"(f.y) : "l"(v));
    return f;
}

// ---------------- fused weight transpose ----------------
__global__ void tr_all_kernel(const float* __restrict__ qw, const float* __restrict__ kw,
                              const float* __restrict__ ow, const float* __restrict__ wih,
                              const float* __restrict__ c1, const float* __restrict__ c2) {
    int idx = blockIdx.x * 256 + threadIdx.x;
    if (idx < 16384) { g_qwT[(idx & 127) * 128 + (idx >> 7)] = qw[idx]; return; }
    idx -= 16384;
    if (idx < 16384) { g_kwT[(idx & 127) * 128 + (idx >> 7)] = kw[idx]; return; }
    idx -= 16384;
    if (idx < 8192)  { int r = idx >> 6, c = idx & 63; g_outwT[c * 128 + r] = ow[idx]; return; }
    idx -= 8192;
    if (idx < 49152) { int r = idx >> 7, c = idx & 127; g_wihT[c * 384 + r] = wih[idx]; return; }
    idx -= 49152;
    if (idx < 16384) { g_c1T[(idx & 127) * 128 + (idx >> 7)] = c1[idx]; return; }
    idx -= 16384;
    if (idx < 16384) { g_c2T[(idx & 127) * 128 + (idx >> 7)] = c2[idx]; return; }
}

// ---------------- proj: 16 rows per block, 256 threads, f32x2 ----------------
__global__ __launch_bounds__(256) void proj_kernel(
    const float* __restrict__ timesteps,
    const float* __restrict__ lin_w, const float* __restrict__ lin_b,
    const float* __restrict__ per_w, const float* __restrict__ per_b,
    const float* __restrict__ q_b, const float* __restrict__ q_g,
    const float* __restrict__ q_be,
    const float* __restrict__ k_b, const float* __restrict__ k_g,
    const float* __restrict__ k_be) {
    __shared__ float tv_s[16];
    __shared__ float emb_s[16 * 128];
    __shared__ u64 emb_p[1024];
    __shared__ float acc_s[16 * 128];
    int tid = threadIdx.x;
    int is_key = (blockIdx.x >= 8);
    int row0 = blockIdx.x * 16;

    if (tid < 16) {
        int u = row0 + tid;
        tv_s[tid] = is_key ? timesteps[u - 128] : (float)u * (1.0f / 127.0f);
    }
    __syncthreads();

    float lw = lin_w[0], lb = lin_b[0];
    #pragma unroll
    for (int s = 0; s < 8; s++) {
        int li = tid + s * 256;
        int r16 = li >> 7, col = li & 127;
        float tv = tv_s[r16];
        float ev = (col == 0) ? fmaf(tv, lw, lb)
                              : __sinf(fmaf(tv, per_w[col - 1], per_b[col - 1]));
        emb_s[li] = ev;
    }
    __syncthreads();

    #pragma unroll
    for (int s = 0; s < 4; s++) {
        int idx = tid + s * 256;
        int rg = idx >> 9, rem = idx & 511, r2 = rem >> 7, i = rem & 127;
        emb_p[idx] = pack2(emb_s[(rg * 8 + r2) * 128 + i],
                           emb_s[(rg * 8 + r2 + 4) * 128 + i]);
    }
    __syncthreads();

    const float* wT   = is_key ? g_kwT : g_qwT;
    const float* bias = is_key ? k_b : q_b;
    int rg = tid >> 7, ltid = tid & 127;
    float bv = bias[ltid];
    u64 acc2[4];
    #pragma unroll
    for (int r2 = 0; r2 < 4; r2++) acc2[r2] = pack2(bv, bv);
    const u64* ep = emb_p + rg * 512;
    #pragma unroll 8
    for (int i = 0; i < 128; i++) {
        float wv = wT[i * 128 + ltid];
        u64 w2 = pack2(wv, wv);
        #pragma unroll
        for (int r2 = 0; r2 < 4; r2++) acc2[r2] = fma2(ep[r2 * 128 + i], w2, acc2[r2]);
    }
    #pragma unroll
    for (int r2 = 0; r2 < 4; r2++) {
        float2 f = unpack2(acc2[r2]);
        acc_s[(rg * 8 + r2) * 128 + ltid]     = f.x;
        acc_s[(rg * 8 + r2 + 4) * 128 + ltid] = f.y;
    }
    __syncthreads();

    int warp = tid >> 5, lane = tid & 31;
    if (warp < 8) {
        const float* gg = is_key ? k_g : q_g;
        const float* bb = is_key ? k_be : q_be;
        #pragma unroll
        for (int rr = 0; rr < 2; rr++) {
            int r16 = warp + rr * 8;
            const float* arow = acc_s + r16 * 128;
            float v[4], s = 0.f, sq = 0.f;
            #pragma unroll
            for (int k = 0; k < 4; k++) {
                v[k] = arow[lane + 32 * k];
                s += v[k];
                sq = fmaf(v[k], v[k], sq);
            }
            #pragma unroll
            for (int o = 16; o > 0; o >>= 1) {
                s  += __shfl_xor_sync(0xffffffffu, s, o);
                sq += __shfl_xor_sync(0xffffffffu, sq, o);
            }
            float mean = s * (1.0f / 128.0f);
            float var = sq * (1.0f / 128.0f) - mean * mean;
            float rs = rsqrtf(var + EPSLN);
            int u = row0 + r16;
            #pragma unroll
            for (int k = 0; k < 4; k++) {
                int col = lane + 32 * k;
                float y = fmaf((v[k] - mean) * rs, gg[col], bb[col]);
                if (is_key) {
                    int idx = u - 128;
                    int b = idx >> 9, t = idx & 511;
                    g_kT[b * 65536 + col * 512 + t] = y;
                } else {
                    g_q[u * 128 + col] = y;
                }
            }
        }
    }
}

// ---------------- FUSED: scores + softmax + masked attention + LN + out + gi GEMM ----------------
__global__ __launch_bounds__(384) void attn_gi_kernel(
    const float* __restrict__ input, const float* __restrict__ mask,
    const float* __restrict__ attn_g, const float* __restrict__ attn_b,
    const float* __restrict__ out_b, const float* __restrict__ out_g,
    const float* __restrict__ out_be, const float* __restrict__ gru_bih) {
    __shared__ __align__(16) char sbuf[33024];
    u64*   q_p   = reinterpret_cast<u64*>(sbuf);            // [1024] phase A
    u64*   o_p   = reinterpret_cast<u64*>(sbuf);            // [512]  phase D
    float* e_s   = reinterpret_cast<float*>(sbuf + 8192);   // [4096] phase A,B
    float* w_s   = reinterpret_cast<float*>(sbuf + 8192);   // [3072] phase D
    float* att_s = reinterpret_cast<float*>(sbuf + 24576);  // [512]
    float* x2_s  = reinterpret_cast<float*>(sbuf + 26624);  // [512]
    float* o_s   = reinterpret_cast<float*>(sbuf + 28672);  // [1024]
    float* wred  = reinterpret_cast<float*>(sbuf + 32768);  // [64]

    int tid = threadIdx.x;
    int warp = tid >> 5, lane = tid & 31;
    int b = blockIdx.x >> 4;
    int qg = blockIdx.x & 15;

    for (int idx = tid; idx < 1024; idx += 384) {
        float v = g_q[qg * 1024 + idx];
        q_p[idx] = pack2(v, v);
    }
    __syncthreads();

    u64 acc2[8];
    if (tid < 256) {
        #pragma unroll
        for (int j = 0; j < 8; j++) acc2[j] = 0ull;
        const u64* kTb = reinterpret_cast<const u64*>(g_kT + b * 65536);
        #pragma unroll 8
        for (int e = 0; e < 128; e++) {
            u64 kv = kTb[e * 256 + tid];
            #pragma unroll
            for (int j = 0; j < 8; j++)
                acc2[j] = fma2(q_p[j * 128 + e], kv, acc2[j]);
        }
        #pragma unroll
        for (int j = 0; j < 8; j++) {
            float2 a = unpack2(acc2[j]);
            float m = fmaxf(a.x, a.y);
            #pragma unroll
            for (int o = 16; o > 0; o >>= 1) m = fmaxf(m, __shfl_xor_sync(0xffffffffu, m, o));
            if (lane == 0) wred[j * 8 + warp] = m;
        }
    }
    __syncthreads();
    if (tid < 256) {
        const float scale = 0.08838834764831845f;
        int t0 = tid * 2;
        #pragma unroll
        for (int j = 0; j < 8; j++) {
            float M = wred[j * 8];
            #pragma unroll
            for (int w = 1; w < 8; w++) M = fmaxf(M, wred[j * 8 + w]);
            float2 a = unpack2(acc2[j]);
            e_s[j * 512 + t0]     = __expf((a.x - M) * scale);
            e_s[j * 512 + t0 + 1] = __expf((a.y - M) * scale);
        }
    }
    __syncthreads();

    for (int c = warp; c < 32; c += 12) {
        const float* mrow = mask + (b * 32 + c) * 512;
        const float* irow = input + (b * 32 + c) * 512;
        float mv[16], miv[16];
        #pragma unroll
        for (int s = 0; s < 16; s++) {
            int t = lane + s * 32;
            float m = 1.0f - mrow[t];
            mv[s] = m;
            miv[s] = m * irow[t];
        }
        #pragma unroll
        for (int j = 0; j < 8; j++) {
            const float* erow = e_s + j * 512 + lane;
            float num = 0.f, den = 0.f;
            #pragma unroll
            for (int s = 0; s < 16; s++) {
                float e = erow[s * 32];
                num = fmaf(e, miv[s], num);
                den = fmaf(e, mv[s], den);
            }
            #pragma unroll
            for (int o = 16; o > 0; o >>= 1) {
                num += __shfl_down_sync(0xffffffffu, num, o);
                den += __shfl_down_sync(0xffffffffu, den, o);
            }
            if (lane == 0) {
                att_s[j * 64 + c]      = den > 0.f ? num / den : 0.f;
                att_s[j * 64 + 32 + c] = den > 0.f ? 1.f : 0.f;
            }
        }
    }
    __syncthreads();

    if (warp < 8) {
        const float2* arow = reinterpret_cast<const float2*>(att_s + warp * 64);
        float2 v = arow[lane];
        float s = v.x + v.y;
        float sq = fmaf(v.x, v.x, v.y * v.y);
        #pragma unroll
        for (int o = 16; o > 0; o >>= 1) {
            s  += __shfl_xor_sync(0xffffffffu, s, o);
            sq += __shfl_xor_sync(0xffffffffu, sq, o);
        }
        float mean = s * (1.0f / 64.0f);
        float var = sq * (1.0f / 64.0f) - mean * mean;
        float rs = rsqrtf(var + EPSLN);
        x2_s[warp * 64 + lane * 2]     = fmaf((v.x - mean) * rs, attn_g[lane * 2], attn_b[lane * 2]);
        x2_s[warp * 64 + lane * 2 + 1] = fmaf((v.y - mean) * rs, attn_g[lane * 2 + 1], attn_b[lane * 2 + 1]);
        __syncwarp();

        float acc[4], s2 = 0.f, sq2 = 0.f;
        #pragma unroll
        for (int k = 0; k < 4; k++) acc[k] = out_b[lane + 32 * k];
        const float* x2r = x2_s + warp * 64;
        #pragma unroll 8
        for (int i = 0; i < 64; i++) {
            float x = x2r[i];
            #pragma unroll
            for (int k = 0; k < 4; k++)
                acc[k] = fmaf(x, g_outwT[i * 128 + lane + 32 * k], acc[k]);
        }
        #pragma unroll
        for (int k = 0; k < 4; k++) { s2 += acc[k]; sq2 = fmaf(acc[k], acc[k], sq2); }
        #pragma unroll
        for (int o = 16; o > 0; o >>= 1) {
            s2  += __shfl_xor_sync(0xffffffffu, s2, o);
            sq2 += __shfl_xor_sync(0xffffffffu, sq2, o);
        }
        float mean2 = s2 * (1.0f / 128.0f);
        float var2 = sq2 * (1.0f / 128.0f) - mean2 * mean2;
        float rs2 = rsqrtf(var2 + EPSLN);
        #pragma unroll
        for (int k = 0; k < 4; k++) {
            int col = lane + 32 * k;
            o_s[warp * 128 + col] = fmaf((acc[k] - mean2) * rs2, out_g[col], out_be[col]);
        }
    }
    __syncthreads();

    for (int idx = tid; idx < 512; idx += 384) {
        int r2 = idx >> 7, i = idx & 127;
        o_p[idx] = pack2(o_s[r2 * 128 + i], o_s[(r2 + 4) * 128 + i]);
    }

    u64 accg[4];
    float bv = gru_bih[tid];
    #pragma unroll
    for (int r2 = 0; r2 < 4; r2++) accg[r2] = pack2(bv, bv);
    #pragma unroll 1
    for (int tile = 0; tile < 16; tile++) {
        __syncthreads();
        const float4* src = reinterpret_cast<const float4*>(g_wihT + tile * 8 * 384);
        float4* dst = reinterpret_cast<float4*>(w_s);
        dst[tid] = src[tid];
        dst[tid + 384] = src[tid + 384];
        __syncthreads();
        #pragma unroll
        for (int i = 0; i < 8; i++) {
            float wv = w_s[i * 384 + tid];
            u64 w2 = pack2(wv, wv);
            int ii = tile * 8 + i;
            #pragma unroll
            for (int r2 = 0; r2 < 4; r2++)
                accg[r2] = fma2(o_p[r2 * 128 + ii], w2, accg[r2]);
        }
    }
    #pragma unroll
    for (int r2 = 0; r2 < 4; r2++) {
        float2 f = unpack2(accg[r2]);
        int ntA = qg * 8 + r2, ntB = qg * 8 + r2 + 4;
        g_gi[(ntA * 8 + b) * 384 + tid] = f.x;
        g_gi[(ntB * 8 + b) * 384 + tid] = f.y;
    }
}

// ---------------- GRU: shortened serial tail (pre-barrier sigmoids, reg-held hn/gin) ----------------
__global__ __launch_bounds__(384, 1) void gru_cls_kernel(
    const float* __restrict__ whh, const float* __restrict__ bhh,
    const float* __restrict__ c1b, const float* __restrict__ c2b,
    const float* __restrict__ c3w, const float* __restrict__ c3b,
    float* __restrict__ out) {
    __shared__ __align__(16) float h_s[128];
    __shared__ float r_s[128], z_s[128];
    int tid = threadIdx.x;
    int b = blockIdx.x;

    u64 wp[64];
    const u64* wrow = reinterpret_cast<const u64*>(whh + tid * 128);
    #pragma unroll
    for (int i = 0; i < 64; i++) wp[i] = wrow[i];
    float bh = bhh[tid];
    if (tid < 128) h_s[tid] = 0.f;

    const float* gptr = g_gi + b * 384 + tid;
    int g = tid >> 7, j = tid & 127;
    float giv = gptr[0];

    for (int t = 0; t < 128; t++) {
        __syncthreads();                          // h_s for step t ready; r_s/z_s consumed
        float giv_next = (t < 127) ? gptr[(t + 1) * 3072] : 0.f;
        u64 a0 = 0ull, a1 = 0ull, a2 = 0ull, a3 = 0ull;
        const ulonglong2* h2 = reinterpret_cast<const ulonglong2*>(h_s);
        #pragma unroll 4
        for (int i = 0; i < 16; i++) {
            ulonglong2 hv0 = h2[2 * i], hv1 = h2[2 * i + 1];
            a0 = fma2(wp[4 * i],     hv0.x, a0);
            a1 = fma2(wp[4 * i + 1], hv0.y, a1);
            a2 = fma2(wp[4 * i + 2], hv1.x, a2);
            a3 = fma2(wp[4 * i + 3], hv1.y, a3);
        }
        a0 = add2(a0, a1);
        a2 = add2(a2, a3);
        a0 = add2(a0, a2);
        float2 f = unpack2(a0);
        float accv = f.x + f.y + bh;
        // sigmoids computed pre-barrier (overlap with other warps' dots)
        if (g == 0)      r_s[j] = sigfast(accv + giv);
        else if (g == 1) z_s[j] = sigfast(accv + giv);
        __syncthreads();                          // gates ready AND all h reads done
        if (g == 2) {
            float r = r_s[j];
            float z = z_s[j];
            float n = tanhfast(fmaf(r, accv, giv));   // accv = hn (kept in register)
            h_s[j] = fmaf(z, h_s[j] - n, n);
        }
        giv = giv_next;
    }
    __syncthreads();

    // classifier on h_s (r_s/z_s as scratch)
    if (tid < 128) {
        float a = c1b[tid];
        #pragma unroll 8
        for (int i = 0; i < 128; i++) a = fmaf(h_s[i], g_c1T[i * 128 + tid], a);
        r_s[tid] = fmaxf(a, 0.f);
    }
    __syncthreads();
    if (tid < 128) {
        float a2v = c2b[tid];
        #pragma unroll 8
        for (int i = 0; i < 128; i++) a2v = fmaf(r_s[i], g_c2T[i * 128 + tid], a2v);
        z_s[tid] = fmaxf(a2v, 0.f);
    }
    __syncthreads();
    if (tid < 2) {
        float a3 = c3b[tid];
        #pragma unroll 8
        for (int i = 0; i < 128; i++) a3 = fmaf(z_s[i], c3w[tid * 128 + i], a3);
        out[b * 2 + tid] = a3;
    }
}

// ---------------- launch ----------------
extern "C" void kernel_launch(void* const* d_in, const int* in_sizes, int n_in,
                              void* d_out, int out_size) {
    const float* input  = (const float*)d_in[0];
    const float* mask   = (const float*)d_in[1];
    const float* tsteps = (const float*)d_in[2];
    const float* per_w  = (const float*)d_in[3];
    const float* per_b  = (const float*)d_in[4];
    const float* lin_w  = (const float*)d_in[5];
    const float* lin_b  = (const float*)d_in[6];
    const float* q_w    = (const float*)d_in[7];
    const float* q_b    = (const float*)d_in[8];
    const float* q_g    = (const float*)d_in[9];
    const float* q_be   = (const float*)d_in[10];
    const float* k_w    = (const float*)d_in[11];
    const float* k_b    = (const float*)d_in[12];
    const float* k_g    = (const float*)d_in[13];
    const float* k_be   = (const float*)d_in[14];
    const float* attn_g = (const float*)d_in[15];
    const float* attn_b = (const float*)d_in[16];
    const float* out_w  = (const float*)d_in[17];
    const float* out_b  = (const float*)d_in[18];
    const float* out_g  = (const float*)d_in[19];
    const float* out_be = (const float*)d_in[20];
    const float* wih    = (const float*)d_in[21];
    const float* whh    = (const float*)d_in[22];
    const float* bih    = (const float*)d_in[23];
    const float* bhh    = (const float*)d_in[24];
    const float* c1_w   = (const float*)d_in[25];
    const float* c1_b   = (const float*)d_in[26];
    const float* c2_w   = (const float*)d_in[27];
    const float* c2_b   = (const float*)d_in[28];
    const float* c3_w   = (const float*)d_in[29];
    const float* c3_b   = (const float*)d_in[30];
    float* out = (float*)d_out;

    tr_all_kernel<<<480, 256>>>(q_w, k_w, out_w, wih, c1_w, c2_w);
    proj_kernel<<<264, 256>>>(tsteps, lin_w, lin_b, per_w, per_b,
                              q_b, q_g, q_be, k_b, k_g, k_be);
    attn_gi_kernel<<<128, 384>>>(input, mask, attn_g, attn_b,
                                 out_b, out_g, out_be, bih);
    gru_cls_kernel<<<8, 384>>>(whh, bhh, c1_b, c2_b, c3_w, c3_b, out);
}